// round 8
// baseline (speedup 1.0000x reference)
#include <cuda_runtime.h>

#define NB       262144
#define THREADS  256
#define ROWS_PER_TILE 256           // 8 warps x 32 rows
#define NTILES   (NB / ROWS_PER_TILE)   // 1024
#define GRID_X   148

typedef unsigned long long u64;

// ---- packed f32x2 helpers (SASS FFMA2) ----
__device__ __forceinline__ u64 ffma2(u64 a, u64 b, u64 c) {
    u64 d;
    asm("fma.rn.f32x2 %0, %1, %2, %3;" : "=l"(d) : "l"(a), "l"(b), "l"(c));
    return d;
}
__device__ __forceinline__ u64 fadd2(u64 a, u64 b) {
    u64 d;
    asm("add.rn.f32x2 %0, %1, %2;" : "=l"(d) : "l"(a), "l"(b));
    return d;
}
__device__ __forceinline__ u64 pack2(float lo, float hi) {
    u64 d;
    asm("mov.b64 %0, {%1, %2};" : "=l"(d) : "f"(lo), "f"(hi));
    return d;
}
__device__ __forceinline__ void unpack2(u64 a, float& lo, float& hi) {
    asm("mov.b64 {%0, %1}, %2;" : "=f"(lo), "=f"(hi) : "l"(a));
}
__device__ __forceinline__ float hsum2(u64 a) {
    float lo, hi; unpack2(a, lo, hi); return lo + hi;
}

// ---- smem layout (u64 units) ----
// WfP [0,6144)      : forward  pairs WfP[l][k][p] = {W_l[2p][k+1], W_l[2p+1][k+1]}
// WbP [6144,12288)  : backward pairs WbP[l][j][p] = {W_l[j][2p+1], W_l[j][2p+2]}
// tcP [12288,12384) : t-col pairs    tcP[l][p]    = {W_l[2p][0],   W_l[2p+1][0]}
// bP  [12384,12480) : bias pairs     bP[l][p]     = {b_l[2p],      b_l[2p+1]}
// hd  [12480,28864) : duplicated activations hd[row][k] = {h_k, h_k}, 256 rows x 64
#define U_WF  0
#define U_WB  6144
#define U_TC  12288
#define U_BI  12384
#define U_HD  12480
#define SMEM_U64  (12480 + 256 * 64)   // 28864
#define SMEM_BYTES (SMEM_U64 * 8)      // 230,912 B (cap 232,448)

__global__ void __launch_bounds__(THREADS, 1)
odefunc_kernel(const float* __restrict__ t_p,
               const float* __restrict__ z,
               const float* __restrict__ e,
               const float* __restrict__ W0g, const float* __restrict__ b0g,
               const float* __restrict__ W1g, const float* __restrict__ b1g,
               const float* __restrict__ W2g, const float* __restrict__ b2g,
               float* __restrict__ out)
{
    extern __shared__ __align__(16) u64 sm[];

    const int tid  = threadIdx.x;
    const int wid  = tid >> 5;
    const int lane = tid & 31;
    const float t  = t_p[0];

    // ---- one-time weight staging per persistent CTA (layouts proven in R7) ----
    {
        float* WfF = reinterpret_cast<float*>(sm + U_WF);
        float* WbF = reinterpret_cast<float*>(sm + U_WB);
        float* tcF = reinterpret_cast<float*>(sm + U_TC);
        const float* Wg[3] = { W0g, W1g, W2g };
        const float* bg[3] = { b0g, b1g, b2g };
#pragma unroll 1
        for (int l = 0; l < 3; ++l) {
            for (int idx = tid; idx < 4096; idx += THREADS) {
                int j = idx >> 6, k = idx & 63;
                float w = Wg[l][j * 65 + k + 1];
                WfF[((l * 64 + k) * 32 + (j >> 1)) * 2 + (j & 1)] = w;
                WbF[((l * 64 + j) * 32 + (k >> 1)) * 2 + (k & 1)] = w;
            }
            if (tid < 64) {
                tcF[(l * 32 + (tid >> 1)) * 2 + (tid & 1)] = Wg[l][tid * 65];
            }
        }
        if (tid < 96) {
            int l = tid >> 5, p = tid & 31;
            sm[U_BI + tid] = pack2(bg[l][2 * p], bg[l][2 * p + 1]);
        }
    }
    __syncthreads();

    const u64 tt = pack2(t, t);
    u64* hd = sm + U_HD + wid * (32 * 64);   // this warp's 32 rows x 64 units

    u64 acc[32];

    for (int tile = blockIdx.x; tile < NTILES; tile += GRID_X) {
        const size_t rowbase = (size_t)tile * ROWS_PER_TILE + wid * 32;

        __syncwarp();   // prior tile's readers done before we overwrite hd

        // ---- stage z rows, duplicated: hd[r][k] = {z_k, z_k} ----
#pragma unroll 4
        for (int r = 0; r < 32; ++r) {
            u64 zp = *reinterpret_cast<const u64*>(z + (rowbase + r) * 64 + 2 * lane);
            float z0, z1; unpack2(zp, z0, z1);
            ulonglong2 val;
            val.x = pack2(z0, z0);
            val.y = pack2(z1, z1);
            *reinterpret_cast<ulonglong2*>(hd + r * 64 + 2 * lane) = val;
        }
        __syncwarp();

        unsigned m0a = 0u, m0b = 0u, m1a = 0u, m1b = 0u;

        // ---- six passes, one rolled body. Lane L owns output pair (2L, 2L+1). ----
#pragma unroll 1
        for (int pass = 0; pass < 6; ++pass) {
            const u64* Wp = sm + ((pass < 3) ? (U_WF + pass * 2048)
                                             : (U_WB + (5 - pass) * 2048));

            if (pass < 3) {
                u64 wt = sm[U_TC + pass * 32 + lane];
                u64 a0 = ffma2(tt, wt, 0ull);        // k=0 term: t * W[:,0]
#pragma unroll
                for (int r = 0; r < 32; ++r) acc[r] = a0;
            } else {
#pragma unroll
                for (int r = 0; r < 32; ++r) acc[r] = 0ull;
            }

            // mainloop: weights in regs (per k-half), activations broadcast from hd
#pragma unroll 1
            for (int half = 0; half < 2; ++half) {
                u64 w[32];
#pragma unroll
                for (int i = 0; i < 32; ++i)
                    w[i] = Wp[(half * 32 + i) * 32 + lane];

#pragma unroll
                for (int r = 0; r < 32; ++r) {
                    const ulonglong2* hp =
                        reinterpret_cast<const ulonglong2*>(hd + r * 64 + half * 32);
#pragma unroll
                    for (int q = 0; q < 16; ++q) {
                        ulonglong2 hq = hp[q];       // {h_2q,h_2q},{h_2q+1,h_2q+1}
                        acc[r] = ffma2(hq.x, w[2 * q],     acc[r]);
                        acc[r] = ffma2(hq.y, w[2 * q + 1], acc[r]);
                    }
                }
            }

            // ---- epilogues ----
            if (pass < 2) {
                // relu + mask bitmasks (bit r = row), bias added once
                u64 bp = sm[U_BI + pass * 32 + lane];
                float b0, b1; unpack2(bp, b0, b1);
                unsigned ma = 0u, mb = 0u;
#pragma unroll
                for (int r = 0; r < 32; ++r) {
                    float v0, v1; unpack2(acc[r], v0, v1);
                    v0 += b0; v1 += b1;
                    ma |= (unsigned)(v0 > 0.0f) << r;
                    mb |= (unsigned)(v1 > 0.0f) << r;
                    float r0 = fmaxf(v0, 0.0f), r1 = fmaxf(v1, 0.0f);
                    ulonglong2 val;
                    val.x = pack2(r0, r0);
                    val.y = pack2(r1, r1);
                    *reinterpret_cast<ulonglong2*>(hd + r * 64 + 2 * lane) = val;
                }
                if (pass == 0) { m0a = ma; m0b = mb; }
                else           { m1a = ma; m1b = mb; }
                __syncwarp();
            } else if (pass == 2) {
                // z_dot -> gmem, then stage cotangent e (duplicated) into hd
                u64 bp = sm[U_BI + 2 * 32 + lane];
                float b0, b1; unpack2(bp, b0, b1);
#pragma unroll
                for (int r = 0; r < 32; ++r) {
                    float v0, v1; unpack2(acc[r], v0, v1);
                    *reinterpret_cast<u64*>(out + (rowbase + r) * 64 + 2 * lane) =
                        pack2(v0 + b0, v1 + b1);
                }
#pragma unroll 4
                for (int r = 0; r < 32; ++r) {
                    u64 ep = *reinterpret_cast<const u64*>(e + (rowbase + r) * 64 + 2 * lane);
                    float e0, e1; unpack2(ep, e0, e1);
                    ulonglong2 val;
                    val.x = pack2(e0, e0);
                    val.y = pack2(e1, e1);
                    *reinterpret_cast<ulonglong2*>(hd + r * 64 + 2 * lane) = val;
                }
                __syncwarp();
            } else if (pass < 5) {
                // apply relu mask (pass 3 -> m1, pass 4 -> m0)
                unsigned ma = (pass == 3) ? m1a : m0a;
                unsigned mb = (pass == 3) ? m1b : m0b;
#pragma unroll
                for (int r = 0; r < 32; ++r) {
                    float v0, v1; unpack2(acc[r], v0, v1);
                    v0 = ((ma >> r) & 1u) ? v0 : 0.0f;
                    v1 = ((mb >> r) & 1u) ? v1 : 0.0f;
                    ulonglong2 val;
                    val.x = pack2(v0, v0);
                    val.y = pack2(v1, v1);
                    *reinterpret_cast<ulonglong2*>(hd + r * 64 + 2 * lane) = val;
                }
                __syncwarp();
            } else {
                // div = dot(gin, e) per row: lane-partial + butterfly reduce
#pragma unroll 1
                for (int r = 0; r < 32; ++r) {
                    u64 ep = *reinterpret_cast<const u64*>(e + (rowbase + r) * 64 + 2 * lane);
                    float s = hsum2(ffma2(ep, acc[r], 0ull));
#pragma unroll
                    for (int off = 16; off > 0; off >>= 1)
                        s += __shfl_xor_sync(0xffffffffu, s, off);
                    if (lane == 0)
                        out[(size_t)NB * 64 + rowbase + r] = -s;
                }
            }
        }
    }
}

extern "C" void kernel_launch(void* const* d_in, const int* in_sizes, int n_in,
                              void* d_out, int out_size) {
    const float* t  = (const float*)d_in[0];
    const float* z  = (const float*)d_in[1];
    const float* e  = (const float*)d_in[2];
    const float* W0 = (const float*)d_in[3];
    const float* b0 = (const float*)d_in[4];
    const float* W1 = (const float*)d_in[5];
    const float* b1 = (const float*)d_in[6];
    const float* W2 = (const float*)d_in[7];
    const float* b2 = (const float*)d_in[8];
    float* out = (float*)d_out;

    cudaFuncSetAttribute(odefunc_kernel,
                         cudaFuncAttributeMaxDynamicSharedMemorySize, SMEM_BYTES);

    odefunc_kernel<<<GRID_X, THREADS, SMEM_BYTES>>>(t, z, e, W0, b0, W1, b1, W2, b2, out);
}

// round 9
// speedup vs baseline: 2.2001x; 2.2001x over previous
#include <cuda_runtime.h>

#define NB       262144
#define THREADS  256
#define ROWS_PER_TILE 256
#define NTILES   (NB / ROWS_PER_TILE)   // 1024
#define GRID_X   148

typedef unsigned long long u64;

// ---- packed f32x2 helpers (SASS FFMA2) ----
__device__ __forceinline__ u64 ffma2(u64 a, u64 b, u64 c) {
    u64 d;
    asm("fma.rn.f32x2 %0, %1, %2, %3;" : "=l"(d) : "l"(a), "l"(b), "l"(c));
    return d;
}
__device__ __forceinline__ u64 fadd2(u64 a, u64 b) {
    u64 d;
    asm("add.rn.f32x2 %0, %1, %2;" : "=l"(d) : "l"(a), "l"(b));
    return d;
}
__device__ __forceinline__ u64 pack2(float lo, float hi) {
    u64 d;
    asm("mov.b64 %0, {%1, %2};" : "=l"(d) : "f"(lo), "f"(hi));
    return d;
}
__device__ __forceinline__ void unpack2(u64 a, float& lo, float& hi) {
    asm("mov.b64 {%0, %1}, %2;" : "=f"(lo), "=f"(hi) : "l"(a));
}
__device__ __forceinline__ float hsum2(u64 a) {
    float lo, hi; unpack2(a, lo, hi); return lo + hi;
}

// ---- smem layout (u64 units) ----
// WfP [0,6144)      : forward  pairs WfP[l][k][p] = {W_l[2p][k+1], W_l[2p+1][k+1]}
// WbP [6144,12288)  : backward pairs WbP[l][j][p] = {W_l[j][2p+1], W_l[j][2p+2]}
// tcP [12288,12384) : t-col pairs    tcP[l][p]    = {W_l[2p][0],   W_l[2p+1][0]}
// bP  [12384,12480) : bias pairs     bP[l][p]     = {b_l[2p],      b_l[2p+1]}
// S0  [12480,20672) : float scr0[64 units][256 rows]   (64 KB)
// S1  [20672,28864) : float scr1[64 units][256 rows]
#define U_WF  0
#define U_WB  6144
#define U_TC  12288
#define U_BI  12384
#define U_S0  12480
#define U_S1  20672
#define SMEM_BYTES (28864 * 8)   // 230,912 B (cap 232,448)

__global__ void __launch_bounds__(THREADS, 1)
odefunc_kernel(const float* __restrict__ t_p,
               const float* __restrict__ z,
               const float* __restrict__ e,
               const float* __restrict__ W0g, const float* __restrict__ b0g,
               const float* __restrict__ W1g, const float* __restrict__ b1g,
               const float* __restrict__ W2g, const float* __restrict__ b2g,
               float* __restrict__ out)
{
    extern __shared__ __align__(16) u64 sm[];
    float* scr0F = reinterpret_cast<float*>(sm + U_S0);
    float* scr1F = reinterpret_cast<float*>(sm + U_S1);

    const int tid  = threadIdx.x;
    const int jh   = tid >> 7;        // output-half owned by this thread
    const int r    = tid & 127;       // local row A; row B = r + 128
    const float t  = t_p[0];

    // ---- one-time weight staging per persistent CTA (layouts proven in R7) ----
    {
        float* WfF = reinterpret_cast<float*>(sm + U_WF);
        float* WbF = reinterpret_cast<float*>(sm + U_WB);
        float* tcF = reinterpret_cast<float*>(sm + U_TC);
        const float* Wg[3] = { W0g, W1g, W2g };
        const float* bg[3] = { b0g, b1g, b2g };
#pragma unroll 1
        for (int l = 0; l < 3; ++l) {
            for (int idx = tid; idx < 4096; idx += THREADS) {
                int j = idx >> 6, k = idx & 63;
                float w = Wg[l][j * 65 + k + 1];
                WfF[((l * 64 + k) * 32 + (j >> 1)) * 2 + (j & 1)] = w;
                WbF[((l * 64 + j) * 32 + (k >> 1)) * 2 + (k & 1)] = w;
            }
            if (tid < 64) {
                tcF[(l * 32 + (tid >> 1)) * 2 + (tid & 1)] = Wg[l][tid * 65];
            }
        }
        if (tid < 96) {
            int l = tid >> 5, p = tid & 31;
            sm[U_BI + tid] = pack2(bg[l][2 * p], bg[l][2 * p + 1]);
        }
    }
    __syncthreads();

    const u64 tt = pack2(t, t);
    u64 aA[16], aB[16];
    unsigned mA0 = 0u, mB0 = 0u, mA1 = 0u, mB1 = 0u;

    for (int tile = blockIdx.x; tile < NTILES; tile += GRID_X) {
        const size_t rowbase = (size_t)tile * ROWS_PER_TILE;
        const size_t gA = rowbase + r, gB = rowbase + r + 128;

        __syncthreads();   // protect S0 from previous tile's div-combine readers

        // ---- stage z (this thread's k-half, both rows) into S0 ----
#pragma unroll 1
        for (int rr = 0; rr < 2; ++rr) {
            const size_t grow = rr ? gB : gA;
            const int    rloc = rr ? (r + 128) : r;
            const float4* zp = reinterpret_cast<const float4*>(z + grow * 64 + jh * 32);
#pragma unroll
            for (int i = 0; i < 8; ++i) {
                float4 q = zp[i];
                scr0F[(jh * 32 + 4 * i + 0) * 256 + rloc] = q.x;
                scr0F[(jh * 32 + 4 * i + 1) * 256 + rloc] = q.y;
                scr0F[(jh * 32 + 4 * i + 2) * 256 + rloc] = q.z;
                scr0F[(jh * 32 + 4 * i + 3) * 256 + rloc] = q.w;
            }
        }

        // ---- six passes: fwd L0,L1,L2 then bwd B2,B1,B0 (rolled body) ----
#pragma unroll 1
        for (int pass = 0; pass < 6; ++pass) {
            __syncthreads();   // pass inputs (written last pass) visible

            const u64* W = sm + ((pass < 3) ? (U_WF + pass * 2048)
                                            : (U_WB + (5 - pass) * 2048))
                              + jh * 16;
            const float* sin  = (pass & 1) ? scr1F : scr0F;
            float*       sout = (pass & 1) ? scr0F : scr1F;

            if (pass < 3) {
                const ulonglong2* tp =
                    reinterpret_cast<const ulonglong2*>(sm + U_TC + pass * 32 + jh * 16);
#pragma unroll
                for (int q = 0; q < 8; ++q) {
                    ulonglong2 tw = tp[q];
                    aA[2*q]   = ffma2(tt, tw.x, 0ull);   // k=0 term: t * W[:,0]
                    aA[2*q+1] = ffma2(tt, tw.y, 0ull);
                    aB[2*q]   = aA[2*q];
                    aB[2*q+1] = aA[2*q+1];
                }
            } else {
#pragma unroll
                for (int p = 0; p < 16; ++p) { aA[p] = 0ull; aB[p] = 0ull; }
            }

            // serial chain: 8 LDS.128 weights (shared by 2 rows) + 2 LDS.32 acts per step
#pragma unroll 8
            for (int k = 0; k < 64; ++k) {
                float hA = sin[k * 256 + r];
                float hB = sin[k * 256 + r + 128];
                u64 hA2 = pack2(hA, hA);
                u64 hB2 = pack2(hB, hB);
                const ulonglong2* wr = reinterpret_cast<const ulonglong2*>(W + k * 32);
#pragma unroll
                for (int q = 0; q < 8; ++q) {
                    ulonglong2 w = wr[q];
                    aA[2*q]   = ffma2(hA2, w.x, aA[2*q]);
                    aA[2*q+1] = ffma2(hA2, w.y, aA[2*q+1]);
                    aB[2*q]   = ffma2(hB2, w.x, aB[2*q]);
                    aB[2*q+1] = ffma2(hB2, w.y, aB[2*q+1]);
                }
            }

            // ---- epilogues ----
            if (pass < 2) {
                // relu + per-thread masks (bits 2i,2i+1 of this thread's 32 units)
                unsigned ma = 0u, mb = 0u;
#pragma unroll
                for (int i = 0; i < 16; ++i) {
                    float b0, b1; unpack2(sm[U_BI + pass * 32 + jh * 16 + i], b0, b1);
                    float v0, v1; unpack2(aA[i], v0, v1);
                    float w0, w1; unpack2(aB[i], w0, w1);
                    v0 += b0; v1 += b1; w0 += b0; w1 += b1;
                    ma |= (unsigned)(v0 > 0.0f) << (2*i);
                    ma |= (unsigned)(v1 > 0.0f) << (2*i+1);
                    mb |= (unsigned)(w0 > 0.0f) << (2*i);
                    mb |= (unsigned)(w1 > 0.0f) << (2*i+1);
                    int u = jh * 32 + 2 * i;
                    sout[u * 256 + r]           = fmaxf(v0, 0.0f);
                    sout[(u + 1) * 256 + r]     = fmaxf(v1, 0.0f);
                    sout[u * 256 + r + 128]     = fmaxf(w0, 0.0f);
                    sout[(u + 1) * 256 + r + 128] = fmaxf(w1, 0.0f);
                }
                if (pass == 0) { mA0 = ma; mB0 = mb; }
                else           { mA1 = ma; mB1 = mb; }
            } else if (pass == 2) {
                // z_dot -> gmem, then stage e into S1 (= sout this pass)
#pragma unroll
                for (int i = 0; i < 16; ++i) {
                    float b0, b1; unpack2(sm[U_BI + 2 * 32 + jh * 16 + i], b0, b1);
                    float v0, v1; unpack2(aA[i], v0, v1);
                    float w0, w1; unpack2(aB[i], w0, w1);
                    *reinterpret_cast<u64*>(out + gA * 64 + jh * 32 + 2 * i) = pack2(v0 + b0, v1 + b1);
                    *reinterpret_cast<u64*>(out + gB * 64 + jh * 32 + 2 * i) = pack2(w0 + b0, w1 + b1);
                }
#pragma unroll 1
                for (int rr = 0; rr < 2; ++rr) {
                    const size_t grow = rr ? gB : gA;
                    const int    rloc = rr ? (r + 128) : r;
                    const float4* ep = reinterpret_cast<const float4*>(e + grow * 64 + jh * 32);
#pragma unroll
                    for (int i = 0; i < 8; ++i) {
                        float4 q = ep[i];
                        sout[(jh * 32 + 4 * i + 0) * 256 + rloc] = q.x;
                        sout[(jh * 32 + 4 * i + 1) * 256 + rloc] = q.y;
                        sout[(jh * 32 + 4 * i + 2) * 256 + rloc] = q.z;
                        sout[(jh * 32 + 4 * i + 3) * 256 + rloc] = q.w;
                    }
                }
            } else if (pass < 5) {
                // apply relu mask (pass 3 -> layer-1 mask, pass 4 -> layer-0 mask)
                unsigned ma = (pass == 3) ? mA1 : mA0;
                unsigned mb = (pass == 3) ? mB1 : mB0;
#pragma unroll
                for (int i = 0; i < 16; ++i) {
                    float v0, v1; unpack2(aA[i], v0, v1);
                    float w0, w1; unpack2(aB[i], w0, w1);
                    v0 = ((ma >> (2*i))   & 1u) ? v0 : 0.0f;
                    v1 = ((ma >> (2*i+1)) & 1u) ? v1 : 0.0f;
                    w0 = ((mb >> (2*i))   & 1u) ? w0 : 0.0f;
                    w1 = ((mb >> (2*i+1)) & 1u) ? w1 : 0.0f;
                    int u = jh * 32 + 2 * i;
                    sout[u * 256 + r]             = v0;
                    sout[(u + 1) * 256 + r]       = v1;
                    sout[u * 256 + r + 128]       = w0;
                    sout[(u + 1) * 256 + r + 128] = w1;
                }
            } else {
                // half-dot with e over this thread's units; combine halves via S0
                const ulonglong2* ea = reinterpret_cast<const ulonglong2*>(e + gA * 64 + jh * 32);
                const ulonglong2* eb = reinterpret_cast<const ulonglong2*>(e + gB * 64 + jh * 32);
                u64 dA = 0ull, dB = 0ull;
#pragma unroll
                for (int q = 0; q < 8; ++q) {
                    ulonglong2 qa = ea[q];
                    ulonglong2 qb = eb[q];
                    dA = ffma2(qa.x, aA[2*q],   dA);
                    dA = ffma2(qa.y, aA[2*q+1], dA);
                    dB = ffma2(qb.x, aB[2*q],   dB);
                    dB = ffma2(qb.y, aB[2*q+1], dB);
                }
                sout[jh * 256 + r]       = hsum2(dA);   // sout = S0 on pass 5
                sout[jh * 256 + r + 128] = hsum2(dB);
                __syncthreads();
                if (jh == 0) {
                    out[(size_t)NB * 64 + gA] = -(sout[r]       + sout[256 + r]);
                    out[(size_t)NB * 64 + gB] = -(sout[r + 128] + sout[256 + r + 128]);
                }
            }
        }
    }
}

extern "C" void kernel_launch(void* const* d_in, const int* in_sizes, int n_in,
                              void* d_out, int out_size) {
    const float* t  = (const float*)d_in[0];
    const float* z  = (const float*)d_in[1];
    const float* e  = (const float*)d_in[2];
    const float* W0 = (const float*)d_in[3];
    const float* b0 = (const float*)d_in[4];
    const float* W1 = (const float*)d_in[5];
    const float* b1 = (const float*)d_in[6];
    const float* W2 = (const float*)d_in[7];
    const float* b2 = (const float*)d_in[8];
    float* out = (float*)d_out;

    cudaFuncSetAttribute(odefunc_kernel,
                         cudaFuncAttributeMaxDynamicSharedMemorySize, SMEM_BYTES);

    odefunc_kernel<<<GRID_X, THREADS, SMEM_BYTES>>>(t, z, e, W0, b0, W1, b1, W2, b2, out);
}

// round 10
// speedup vs baseline: 2.4728x; 1.1239x over previous
#include <cuda_runtime.h>

#define NB       262144
#define THREADS  256
#define ROWS_PER_TILE 256
#define NTILES   (NB / ROWS_PER_TILE)   // 1024
#define GRID_X   148

typedef unsigned long long u64;

// ---- packed f32x2 helpers (SASS FFMA2) ----
__device__ __forceinline__ u64 ffma2(u64 a, u64 b, u64 c) {
    u64 d;
    asm("fma.rn.f32x2 %0, %1, %2, %3;" : "=l"(d) : "l"(a), "l"(b), "l"(c));
    return d;
}
__device__ __forceinline__ u64 pack2(float lo, float hi) {
    u64 d;
    asm("mov.b64 %0, {%1, %2};" : "=l"(d) : "f"(lo), "f"(hi));
    return d;
}
__device__ __forceinline__ void unpack2(u64 a, float& lo, float& hi) {
    asm("mov.b64 {%0, %1}, %2;" : "=f"(lo), "=f"(hi) : "l"(a));
}
__device__ __forceinline__ float hsum2(u64 a) {
    float lo, hi; unpack2(a, lo, hi); return lo + hi;
}

// ---- smem layout (u64 units) ----
// WfP [0,6144)      : forward  pairs WfP[l][k][p] = {W_l[2p][k+1], W_l[2p+1][k+1]}
// WbP [6144,12288)  : backward pairs WbP[l][j][p] = {W_l[j][2p+1], W_l[j][2p+2]}
// tcP [12288,12384) : t-col pairs    tcP[l][p]    = {W_l[2p][0],   W_l[2p+1][0]}
// bP  [12384,12480) : bias pairs     bP[l][p]     = {b_l[2p],      b_l[2p+1]}
// S0  [12480,20672) : u64 scr0[32 pair-units][256 rows]   (64 KB)
// S1  [20672,28864) : u64 scr1[32 pair-units][256 rows]
#define U_WF  0
#define U_WB  6144
#define U_TC  12288
#define U_BI  12384
#define U_S0  12480
#define U_S1  20672
#define SMEM_BYTES (28864 * 8)   // 230,912 B

__global__ void __launch_bounds__(THREADS, 1)
odefunc_kernel(const float* __restrict__ t_p,
               const float* __restrict__ z,
               const float* __restrict__ e,
               const float* __restrict__ W0g, const float* __restrict__ b0g,
               const float* __restrict__ W1g, const float* __restrict__ b1g,
               const float* __restrict__ W2g, const float* __restrict__ b2g,
               float* __restrict__ out)
{
    extern __shared__ __align__(16) u64 sm[];

    const int tid = threadIdx.x;
    const int jq  = tid >> 6;        // output quarter: pairs jq*8 .. jq*8+7
    const int r   = tid & 63;        // base row; rows are r + 64*rr, rr=0..3
    const float t = t_p[0];

    // ---- one-time weight staging per persistent CTA (layouts proven R7/R9) ----
    {
        float* WfF = reinterpret_cast<float*>(sm + U_WF);
        float* WbF = reinterpret_cast<float*>(sm + U_WB);
        float* tcF = reinterpret_cast<float*>(sm + U_TC);
        const float* Wg[3] = { W0g, W1g, W2g };
        const float* bg[3] = { b0g, b1g, b2g };
#pragma unroll 1
        for (int l = 0; l < 3; ++l) {
            for (int idx = tid; idx < 4096; idx += THREADS) {
                int j = idx >> 6, k = idx & 63;
                float w = Wg[l][j * 65 + k + 1];
                WfF[((l * 64 + k) * 32 + (j >> 1)) * 2 + (j & 1)] = w;
                WbF[((l * 64 + j) * 32 + (k >> 1)) * 2 + (k & 1)] = w;
            }
            if (tid < 64) {
                tcF[(l * 32 + (tid >> 1)) * 2 + (tid & 1)] = Wg[l][tid * 65];
            }
        }
        if (tid < 96) {
            int l = tid >> 5, p = tid & 31;
            sm[U_BI + tid] = pack2(bg[l][2 * p], bg[l][2 * p + 1]);
        }
    }
    __syncthreads();

    const u64 tt = pack2(t, t);
    u64 acc[4][8];                    // [row rr][pair i]
    u64 mask0 = 0ull, mask1 = 0ull;   // bit (rr*16 + 2i (+1))

    for (int tile = blockIdx.x; tile < NTILES; tile += GRID_X) {
        const size_t rowbase = (size_t)tile * ROWS_PER_TILE;

        __syncthreads();   // prev tile's div-combine readers done with S0

        // ---- stage z: this thread's 16-float slice of its 4 rows into S0 ----
#pragma unroll
        for (int rr = 0; rr < 4; ++rr) {
            const int rloc = r + 64 * rr;
            const ulonglong2* zp =
                reinterpret_cast<const ulonglong2*>(z + (rowbase + rloc) * 64 + jq * 16);
#pragma unroll
            for (int q = 0; q < 4; ++q) {
                ulonglong2 v = zp[q];
                sm[U_S0 + (jq * 8 + 2 * q)     * 256 + rloc] = v.x;
                sm[U_S0 + (jq * 8 + 2 * q + 1) * 256 + rloc] = v.y;
            }
        }

        // ---- six passes: fwd L0,L1,L2 then bwd B2,B1,B0 (rolled body) ----
#pragma unroll 1
        for (int pass = 0; pass < 6; ++pass) {
            __syncthreads();   // pass inputs visible

            const u64* W = sm + ((pass < 3) ? (U_WF + pass * 2048)
                                            : (U_WB + (5 - pass) * 2048));
            const u64* sin  = sm + ((pass & 1) ? U_S1 : U_S0);
            u64*       sout = sm + ((pass & 1) ? U_S0 : U_S1);

            // init accumulators
            if (pass < 3) {
                const ulonglong2* tp =
                    reinterpret_cast<const ulonglong2*>(sm + U_TC + pass * 32 + jq * 8);
#pragma unroll
                for (int q = 0; q < 4; ++q) {
                    ulonglong2 tw = tp[q];
                    u64 a = ffma2(tt, tw.x, 0ull);   // k=0 term: t * W[:,0]
                    u64 b = ffma2(tt, tw.y, 0ull);
#pragma unroll
                    for (int rr = 0; rr < 4; ++rr) { acc[rr][2*q] = a; acc[rr][2*q+1] = b; }
                }
            } else {
#pragma unroll
                for (int rr = 0; rr < 4; ++rr)
#pragma unroll
                    for (int i = 0; i < 8; ++i) acc[rr][i] = 0ull;
            }

            // mainloop over input pair-units u (k = 2u, 2u+1), strictly ascending
#pragma unroll 4
            for (int u = 0; u < 32; ++u) {
                u64 hlo[4], hhi[4];
#pragma unroll
                for (int rr = 0; rr < 4; ++rr) {
                    u64 hp = sin[u * 256 + r + 64 * rr];   // {h_2u, h_2u+1}
                    float lo, hi; unpack2(hp, lo, hi);
                    hlo[rr] = pack2(lo, lo);
                    hhi[rr] = pack2(hi, hi);
                }
                const ulonglong2* w0 =
                    reinterpret_cast<const ulonglong2*>(W + (2*u)     * 32 + jq * 8);
                const ulonglong2* w1 =
                    reinterpret_cast<const ulonglong2*>(W + (2*u + 1) * 32 + jq * 8);
                // k = 2u
#pragma unroll
                for (int q = 0; q < 4; ++q) {
                    ulonglong2 w = w0[q];
#pragma unroll
                    for (int rr = 0; rr < 4; ++rr) {
                        acc[rr][2*q]   = ffma2(hlo[rr], w.x, acc[rr][2*q]);
                        acc[rr][2*q+1] = ffma2(hlo[rr], w.y, acc[rr][2*q+1]);
                    }
                }
                // k = 2u + 1
#pragma unroll
                for (int q = 0; q < 4; ++q) {
                    ulonglong2 w = w1[q];
#pragma unroll
                    for (int rr = 0; rr < 4; ++rr) {
                        acc[rr][2*q]   = ffma2(hhi[rr], w.x, acc[rr][2*q]);
                        acc[rr][2*q+1] = ffma2(hhi[rr], w.y, acc[rr][2*q+1]);
                    }
                }
            }

            // ---- epilogues ----
            if (pass < 2) {
                u64 m = 0ull;
#pragma unroll
                for (int i = 0; i < 8; ++i) {
                    float b0, b1; unpack2(sm[U_BI + pass * 32 + jq * 8 + i], b0, b1);
#pragma unroll
                    for (int rr = 0; rr < 4; ++rr) {
                        float v0, v1; unpack2(acc[rr][i], v0, v1);
                        v0 += b0; v1 += b1;
                        m |= (u64)(v0 > 0.0f) << (rr * 16 + 2 * i);
                        m |= (u64)(v1 > 0.0f) << (rr * 16 + 2 * i + 1);
                        sout[(jq * 8 + i) * 256 + r + 64 * rr] =
                            pack2(fmaxf(v0, 0.0f), fmaxf(v1, 0.0f));
                    }
                }
                if (pass == 0) mask0 = m; else mask1 = m;
            } else if (pass == 2) {
                // z_dot -> gmem
#pragma unroll
                for (int rr = 0; rr < 4; ++rr) {
                    const int rloc = r + 64 * rr;
                    float4* o4 = reinterpret_cast<float4*>(out + (rowbase + rloc) * 64 + jq * 16);
#pragma unroll
                    for (int q = 0; q < 4; ++q) {
                        float b0, b1; unpack2(sm[U_BI + 2 * 32 + jq * 8 + 2 * q],     b0, b1);
                        float b2, b3; unpack2(sm[U_BI + 2 * 32 + jq * 8 + 2 * q + 1], b2, b3);
                        float v0, v1, v2, v3;
                        unpack2(acc[rr][2*q],   v0, v1);
                        unpack2(acc[rr][2*q+1], v2, v3);
                        o4[q] = make_float4(v0 + b0, v1 + b1, v2 + b2, v3 + b3);
                    }
                }
                // stage cotangent e into sout (= S1 this pass)
#pragma unroll
                for (int rr = 0; rr < 4; ++rr) {
                    const int rloc = r + 64 * rr;
                    const ulonglong2* ep =
                        reinterpret_cast<const ulonglong2*>(e + (rowbase + rloc) * 64 + jq * 16);
#pragma unroll
                    for (int q = 0; q < 4; ++q) {
                        ulonglong2 v = ep[q];
                        sout[(jq * 8 + 2 * q)     * 256 + rloc] = v.x;
                        sout[(jq * 8 + 2 * q + 1) * 256 + rloc] = v.y;
                    }
                }
            } else if (pass < 5) {
                u64 m = (pass == 3) ? mask1 : mask0;
#pragma unroll
                for (int i = 0; i < 8; ++i) {
#pragma unroll
                    for (int rr = 0; rr < 4; ++rr) {
                        float v0, v1; unpack2(acc[rr][i], v0, v1);
                        v0 = ((m >> (rr * 16 + 2 * i))     & 1ull) ? v0 : 0.0f;
                        v1 = ((m >> (rr * 16 + 2 * i + 1)) & 1ull) ? v1 : 0.0f;
                        sout[(jq * 8 + i) * 256 + r + 64 * rr] = pack2(v0, v1);
                    }
                }
            } else {
                // partial div over this thread's 16-float slice; combine via S0
                float* partial = reinterpret_cast<float*>(sout);   // sout = S0 on pass 5
#pragma unroll
                for (int rr = 0; rr < 4; ++rr) {
                    const int rloc = r + 64 * rr;
                    const u64* ep =
                        reinterpret_cast<const u64*>(e + (rowbase + rloc) * 64 + jq * 16);
                    u64 d = 0ull;
#pragma unroll
                    for (int i = 0; i < 8; ++i)
                        d = ffma2(ep[i], acc[rr][i], d);
                    partial[jq * 256 + rloc] = hsum2(d);
                }
                __syncthreads();
                if (jq == 0) {
#pragma unroll
                    for (int rr = 0; rr < 4; ++rr) {
                        const int rloc = r + 64 * rr;
                        float s = partial[rloc] + partial[256 + rloc]
                                + partial[512 + rloc] + partial[768 + rloc];
                        out[(size_t)NB * 64 + rowbase + rloc] = -s;
                    }
                }
            }
        }
    }
}

extern "C" void kernel_launch(void* const* d_in, const int* in_sizes, int n_in,
                              void* d_out, int out_size) {
    const float* t  = (const float*)d_in[0];
    const float* z  = (const float*)d_in[1];
    const float* e  = (const float*)d_in[2];
    const float* W0 = (const float*)d_in[3];
    const float* b0 = (const float*)d_in[4];
    const float* W1 = (const float*)d_in[5];
    const float* b1 = (const float*)d_in[6];
    const float* W2 = (const float*)d_in[7];
    const float* b2 = (const float*)d_in[8];
    float* out = (float*)d_out;

    cudaFuncSetAttribute(odefunc_kernel,
                         cudaFuncAttributeMaxDynamicSharedMemorySize, SMEM_BYTES);

    odefunc_kernel<<<GRID_X, THREADS, SMEM_BYTES>>>(t, z, e, W0, b0, W1, b1, W2, b2, out);
}

// round 11
// speedup vs baseline: 2.4895x; 1.0068x over previous
#include <cuda_runtime.h>

#define NB       262144
#define THREADS  512
#define ROWS_PER_TILE 256
#define NTILES   (NB / ROWS_PER_TILE)   // 1024
#define GRID_X   148

typedef unsigned long long u64;

// ---- packed f32x2 helpers (SASS FFMA2) ----
__device__ __forceinline__ u64 ffma2(u64 a, u64 b, u64 c) {
    u64 d;
    asm("fma.rn.f32x2 %0, %1, %2, %3;" : "=l"(d) : "l"(a), "l"(b), "l"(c));
    return d;
}
__device__ __forceinline__ u64 pack2(float lo, float hi) {
    u64 d;
    asm("mov.b64 %0, {%1, %2};" : "=l"(d) : "f"(lo), "f"(hi));
    return d;
}
__device__ __forceinline__ void unpack2(u64 a, float& lo, float& hi) {
    asm("mov.b64 {%0, %1}, %2;" : "=f"(lo), "=f"(hi) : "l"(a));
}
__device__ __forceinline__ float hsum2(u64 a) {
    float lo, hi; unpack2(a, lo, hi); return lo + hi;
}

// ---- smem layout (u64 units) ----
// WfP [0,6144)      : forward  pairs WfP[l][k][p] = {W_l[2p][k+1], W_l[2p+1][k+1]}
// WbP [6144,12288)  : backward pairs WbP[l][j][p] = {W_l[j][2p+1], W_l[j][2p+2]}
// tcP [12288,12384) : t-col pairs    tcP[l][p]    = {W_l[2p][0],   W_l[2p+1][0]}
// bP  [12384,12480) : bias pairs     bP[l][p]     = {b_l[2p],      b_l[2p+1]}
// S0  [12480,20672) : u64 scr0[32 pair-units][256 rows]   (64 KB)
// S1  [20672,28864) : u64 scr1[32 pair-units][256 rows]
#define U_WF  0
#define U_WB  6144
#define U_TC  12288
#define U_BI  12384
#define U_S0  12480
#define U_S1  20672
#define SMEM_BYTES (28864 * 8)   // 230,912 B

__global__ void __launch_bounds__(THREADS, 1)
odefunc_kernel(const float* __restrict__ t_p,
               const float* __restrict__ z,
               const float* __restrict__ e,
               const float* __restrict__ W0g, const float* __restrict__ b0g,
               const float* __restrict__ W1g, const float* __restrict__ b1g,
               const float* __restrict__ W2g, const float* __restrict__ b2g,
               float* __restrict__ out)
{
    extern __shared__ __align__(16) u64 sm[];

    const int tid = threadIdx.x;
    const int jo  = tid >> 6;        // output eighth: pairs jo*4 .. jo*4+3 (warp-uniform)
    const int r   = tid & 63;        // base row; rows are r + 64*rr, rr=0..3
    const float t = t_p[0];

    // ---- one-time weight staging per persistent CTA (layouts proven R7/R9/R10) ----
    {
        float* WfF = reinterpret_cast<float*>(sm + U_WF);
        float* WbF = reinterpret_cast<float*>(sm + U_WB);
        float* tcF = reinterpret_cast<float*>(sm + U_TC);
        const float* Wg[3] = { W0g, W1g, W2g };
        const float* bg[3] = { b0g, b1g, b2g };
#pragma unroll 1
        for (int l = 0; l < 3; ++l) {
            for (int idx = tid; idx < 4096; idx += THREADS) {
                int j = idx >> 6, k = idx & 63;
                float w = Wg[l][j * 65 + k + 1];
                WfF[((l * 64 + k) * 32 + (j >> 1)) * 2 + (j & 1)] = w;
                WbF[((l * 64 + j) * 32 + (k >> 1)) * 2 + (k & 1)] = w;
            }
            if (tid < 64) {
                tcF[(l * 32 + (tid >> 1)) * 2 + (tid & 1)] = Wg[l][tid * 65];
            }
        }
        if (tid < 96) {
            int l = tid >> 5, p = tid & 31;
            sm[U_BI + tid] = pack2(bg[l][2 * p], bg[l][2 * p + 1]);
        }
    }
    __syncthreads();

    const u64 tt = pack2(t, t);
    u64 acc[4][4];                      // [row rr][pair i]
    unsigned mask0 = 0u, mask1 = 0u;    // bit (rr*8 + 2i (+1))

    for (int tile = blockIdx.x; tile < NTILES; tile += GRID_X) {
        const size_t rowbase = (size_t)tile * ROWS_PER_TILE;

        __syncthreads();   // prev tile's div-combine readers done with S0

        // ---- stage z: this thread's 8-float slice of its 4 rows into S0 ----
#pragma unroll
        for (int rr = 0; rr < 4; ++rr) {
            const int rloc = r + 64 * rr;
            const ulonglong2* zp =
                reinterpret_cast<const ulonglong2*>(z + (rowbase + rloc) * 64 + jo * 8);
#pragma unroll
            for (int q = 0; q < 2; ++q) {
                ulonglong2 v = zp[q];
                sm[U_S0 + (jo * 4 + 2 * q)     * 256 + rloc] = v.x;
                sm[U_S0 + (jo * 4 + 2 * q + 1) * 256 + rloc] = v.y;
            }
        }

        // ---- six passes: fwd L0,L1,L2 then bwd B2,B1,B0 (rolled body) ----
#pragma unroll 1
        for (int pass = 0; pass < 6; ++pass) {
            __syncthreads();   // pass inputs visible

            const u64* W = sm + ((pass < 3) ? (U_WF + pass * 2048)
                                            : (U_WB + (5 - pass) * 2048));
            const u64* sin  = sm + ((pass & 1) ? U_S1 : U_S0);
            u64*       sout = sm + ((pass & 1) ? U_S0 : U_S1);

            // init accumulators
            if (pass < 3) {
                const ulonglong2* tp =
                    reinterpret_cast<const ulonglong2*>(sm + U_TC + pass * 32 + jo * 4);
#pragma unroll
                for (int q = 0; q < 2; ++q) {
                    ulonglong2 tw = tp[q];
                    u64 a = ffma2(tt, tw.x, 0ull);   // k=0 term: t * W[:,0]
                    u64 b = ffma2(tt, tw.y, 0ull);
#pragma unroll
                    for (int rr = 0; rr < 4; ++rr) { acc[rr][2*q] = a; acc[rr][2*q+1] = b; }
                }
            } else {
#pragma unroll
                for (int rr = 0; rr < 4; ++rr)
#pragma unroll
                    for (int i = 0; i < 4; ++i) acc[rr][i] = 0ull;
            }

            // mainloop over input pair-units u (k = 2u, 2u+1), strictly ascending
#pragma unroll 4
            for (int u = 0; u < 32; ++u) {
                u64 hlo[4], hhi[4];
#pragma unroll
                for (int rr = 0; rr < 4; ++rr) {
                    u64 hp = sin[u * 256 + r + 64 * rr];   // {h_2u, h_2u+1}
                    float lo, hi; unpack2(hp, lo, hi);
                    hlo[rr] = pack2(lo, lo);
                    hhi[rr] = pack2(hi, hi);
                }
                const ulonglong2* w0 =
                    reinterpret_cast<const ulonglong2*>(W + (2*u)     * 32 + jo * 4);
                const ulonglong2* w1 =
                    reinterpret_cast<const ulonglong2*>(W + (2*u + 1) * 32 + jo * 4);
                // k = 2u
#pragma unroll
                for (int q = 0; q < 2; ++q) {
                    ulonglong2 w = w0[q];
#pragma unroll
                    for (int rr = 0; rr < 4; ++rr) {
                        acc[rr][2*q]   = ffma2(hlo[rr], w.x, acc[rr][2*q]);
                        acc[rr][2*q+1] = ffma2(hlo[rr], w.y, acc[rr][2*q+1]);
                    }
                }
                // k = 2u + 1
#pragma unroll
                for (int q = 0; q < 2; ++q) {
                    ulonglong2 w = w1[q];
#pragma unroll
                    for (int rr = 0; rr < 4; ++rr) {
                        acc[rr][2*q]   = ffma2(hhi[rr], w.x, acc[rr][2*q]);
                        acc[rr][2*q+1] = ffma2(hhi[rr], w.y, acc[rr][2*q+1]);
                    }
                }
            }

            // ---- epilogues ----
            if (pass < 2) {
                unsigned m = 0u;
#pragma unroll
                for (int i = 0; i < 4; ++i) {
                    float b0, b1; unpack2(sm[U_BI + pass * 32 + jo * 4 + i], b0, b1);
#pragma unroll
                    for (int rr = 0; rr < 4; ++rr) {
                        float v0, v1; unpack2(acc[rr][i], v0, v1);
                        v0 += b0; v1 += b1;
                        m |= (unsigned)(v0 > 0.0f) << (rr * 8 + 2 * i);
                        m |= (unsigned)(v1 > 0.0f) << (rr * 8 + 2 * i + 1);
                        sout[(jo * 4 + i) * 256 + r + 64 * rr] =
                            pack2(fmaxf(v0, 0.0f), fmaxf(v1, 0.0f));
                    }
                }
                if (pass == 0) mask0 = m; else mask1 = m;
            } else if (pass == 2) {
                // z_dot -> gmem
#pragma unroll
                for (int rr = 0; rr < 4; ++rr) {
                    const int rloc = r + 64 * rr;
                    float4* o4 = reinterpret_cast<float4*>(out + (rowbase + rloc) * 64 + jo * 8);
#pragma unroll
                    for (int q = 0; q < 2; ++q) {
                        float b0, b1; unpack2(sm[U_BI + 2 * 32 + jo * 4 + 2 * q],     b0, b1);
                        float b2, b3; unpack2(sm[U_BI + 2 * 32 + jo * 4 + 2 * q + 1], b2, b3);
                        float v0, v1, v2, v3;
                        unpack2(acc[rr][2*q],   v0, v1);
                        unpack2(acc[rr][2*q+1], v2, v3);
                        o4[q] = make_float4(v0 + b0, v1 + b1, v2 + b2, v3 + b3);
                    }
                }
                // stage cotangent e into sout (= S1 this pass)
#pragma unroll
                for (int rr = 0; rr < 4; ++rr) {
                    const int rloc = r + 64 * rr;
                    const ulonglong2* ep =
                        reinterpret_cast<const ulonglong2*>(e + (rowbase + rloc) * 64 + jo * 8);
#pragma unroll
                    for (int q = 0; q < 2; ++q) {
                        ulonglong2 v = ep[q];
                        sout[(jo * 4 + 2 * q)     * 256 + rloc] = v.x;
                        sout[(jo * 4 + 2 * q + 1) * 256 + rloc] = v.y;
                    }
                }
            } else if (pass < 5) {
                unsigned m = (pass == 3) ? mask1 : mask0;
#pragma unroll
                for (int i = 0; i < 4; ++i) {
#pragma unroll
                    for (int rr = 0; rr < 4; ++rr) {
                        float v0, v1; unpack2(acc[rr][i], v0, v1);
                        v0 = ((m >> (rr * 8 + 2 * i))     & 1u) ? v0 : 0.0f;
                        v1 = ((m >> (rr * 8 + 2 * i + 1)) & 1u) ? v1 : 0.0f;
                        sout[(jo * 4 + i) * 256 + r + 64 * rr] = pack2(v0, v1);
                    }
                }
            } else {
                // partial div over this thread's 8-float slice; combine via S0
                float* partial = reinterpret_cast<float*>(sout);   // sout = S0 on pass 5
#pragma unroll
                for (int rr = 0; rr < 4; ++rr) {
                    const int rloc = r + 64 * rr;
                    const u64* ep =
                        reinterpret_cast<const u64*>(e + (rowbase + rloc) * 64 + jo * 8);
                    u64 d = 0ull;
#pragma unroll
                    for (int i = 0; i < 4; ++i)
                        d = ffma2(ep[i], acc[rr][i], d);
                    partial[jo * 256 + rloc] = hsum2(d);
                }
                __syncthreads();
                if (jo == 0) {
#pragma unroll
                    for (int rr = 0; rr < 4; ++rr) {
                        const int rloc = r + 64 * rr;
                        float s = 0.0f;
#pragma unroll
                        for (int g = 0; g < 8; ++g)
                            s += partial[g * 256 + rloc];
                        out[(size_t)NB * 64 + rowbase + rloc] = -s;
                    }
                }
            }
        }
    }
}

extern "C" void kernel_launch(void* const* d_in, const int* in_sizes, int n_in,
                              void* d_out, int out_size) {
    const float* t  = (const float*)d_in[0];
    const float* z  = (const float*)d_in[1];
    const float* e  = (const float*)d_in[2];
    const float* W0 = (const float*)d_in[3];
    const float* b0 = (const float*)d_in[4];
    const float* W1 = (const float*)d_in[5];
    const float* b1 = (const float*)d_in[6];
    const float* W2 = (const float*)d_in[7];
    const float* b2 = (const float*)d_in[8];
    float* out = (float*)d_out;

    cudaFuncSetAttribute(odefunc_kernel,
                         cudaFuncAttributeMaxDynamicSharedMemorySize, SMEM_BYTES);

    odefunc_kernel<<<GRID_X, THREADS, SMEM_BYTES>>>(t, z, e, W0, b0, W1, b1, W2, b2, out);
}